// round 9
// baseline (speedup 1.0000x reference)
#include <cuda_runtime.h>
#include <cuda_bf16.h>
#include <cstdint>
#include <cstddef>

// Fixed problem dims: B=4, S=2048 -> M=8192, K=4096, N=4096
#define KDIM 4096
#define NDIM 4096
#define MMAX 8192

#define BM 128
#define BN 128
#define BK 128
#define KT (KDIM / BK)      // 32 k-chunks (128B)
#define KI 18               // k-chunks done by IMMA warps [0, KI)  (must be even)
#define KD (KT - KI)        // k-chunks (128B) done by dp4a warps
#define NPAIR (KI / 2)      // 9 IMMA chunk-pairs per tile
#define ND64 (KD * 2)       // 28 dp4a 64B-chunks per tile

#define TILES_TOT ((MMAX / BM) * (NDIM / BN))  // 2048
#define GRID 148                                // persistent CTAs (1/SM)

#define STAGE_BYTES (BM * BK + BN * BK)        // 32768 (IMMA stage)
#define DP_STAGE 16384                          // dp4a 64B-chunk stage (A 8K + B 8K)
#define SM_DP   (4 * STAGE_BYTES)               // 131072 (IMMA: 4 buffers = 2 pairs)
#define SM_PART (SM_DP + 2 * DP_STAGE)          // 163840
#define PART_STRIDE 132                         // padded int32 row stride
#define SMEM_TOTAL (SM_PART + BM * PART_STRIDE * 4)  // 231424

// -------- device scratch --------
__device__ int8_t g_A8[(size_t)MMAX * KDIM];
__device__ int8_t g_B8[(size_t)NDIM * KDIM];
__device__ float  g_comb[KDIM];
__device__ float  g_sc[NDIM];

// -------- helpers --------
__device__ __forceinline__ uint32_t smem_u32(const void* p) {
    uint32_t a;
    asm("{ .reg .u64 t; cvta.to.shared.u64 t, %1; cvt.u32.u64 %0, t; }" : "=r"(a) : "l"(p));
    return a;
}
__device__ __forceinline__ void cp16(uint32_t s, const void* g) {
    asm volatile("cp.async.cg.shared.global [%0], [%1], 16;" :: "r"(s), "l"(g));
}
__device__ __forceinline__ void ldsm4(uint32_t* d, uint32_t addr) {
    asm volatile("ldmatrix.sync.aligned.m8n8.x4.shared.b16 {%0,%1,%2,%3}, [%4];"
                 : "=r"(d[0]), "=r"(d[1]), "=r"(d[2]), "=r"(d[3]) : "r"(addr));
}
__device__ __forceinline__ void imma(int* c, const uint32_t* a, const uint32_t* b) {
    asm volatile(
        "mma.sync.aligned.m16n8k32.row.col.s32.s8.s8.s32 "
        "{%0,%1,%2,%3}, {%4,%5,%6,%7}, {%8,%9}, {%0,%1,%2,%3};"
        : "+r"(c[0]), "+r"(c[1]), "+r"(c[2]), "+r"(c[3])
        : "r"(a[0]), "r"(a[1]), "r"(a[2]), "r"(a[3]), "r"(b[0]), "r"(b[1]));
}
__device__ __forceinline__ void dp4a_acc(int& c, uint32_t a, uint32_t b) {
    asm volatile("dp4a.s32.s32 %0, %1, %2, %0;" : "+r"(c) : "r"(a), "r"(b));
}
__device__ __forceinline__ void lds128(uint32_t* d, uint32_t addr) {
    asm volatile("ld.shared.v4.b32 {%0,%1,%2,%3}, [%4];"
                 : "=r"(d[0]), "=r"(d[1]), "=r"(d[2]), "=r"(d[3]) : "r"(addr));
}

// -------- preprocessing --------
__global__ void precomp_scales(const float* __restrict__ in_scale,
                               const float* __restrict__ act,
                               const float* __restrict__ w_scale) {
    int i = blockIdx.x * blockDim.x + threadIdx.x;
    float a = act[0];
    if (i < KDIM) g_comb[i] = __fdiv_rn(in_scale[i], a);
    if (i < NDIM) g_sc[i] = a * w_scale[i];
}

__global__ void quant_x(const float* __restrict__ x, int total4) {
    int i = blockIdx.x * blockDim.x + threadIdx.x;
    if (i >= total4) return;
    float4 v = reinterpret_cast<const float4*>(x)[i];
    int col = (i & (KDIM / 4 - 1)) * 4;
    int q0 = min(max(__float2int_rn(v.x * g_comb[col + 0]), -127), 127);
    int q1 = min(max(__float2int_rn(v.y * g_comb[col + 1]), -127), 127);
    int q2 = min(max(__float2int_rn(v.z * g_comb[col + 2]), -127), 127);
    int q3 = min(max(__float2int_rn(v.w * g_comb[col + 3]), -127), 127);
    uint32_t p = (uint32_t)(q0 & 0xFF) | ((uint32_t)(q1 & 0xFF) << 8) |
                 ((uint32_t)(q2 & 0xFF) << 16) | ((uint32_t)(q3 & 0xFF) << 24);
    reinterpret_cast<uint32_t*>(g_A8)[i] = p;
}

__global__ void conv_w(const int* __restrict__ w, int total4) {
    int i = blockIdx.x * blockDim.x + threadIdx.x;
    if (i >= total4) return;
    int4 v = reinterpret_cast<const int4*>(w)[i];
    uint32_t p = (uint32_t)(v.x & 0xFF) | ((uint32_t)(v.y & 0xFF) << 8) |
                 ((uint32_t)(v.z & 0xFF) << 16) | ((uint32_t)(v.w & 0xFF) << 24);
    reinterpret_cast<uint32_t*>(g_B8)[i] = p;
}

// -------- IMMA tile loader (A then B, XOR-swizzled 128B rows, 256 threads) --------
__device__ __forceinline__ void load_stage(uint32_t sm, const char* gA, const char* gB,
                                           int kt, int t) {
    const char* ga = gA + (size_t)kt * BK;
    const char* gb = gB + (size_t)kt * BK;
#pragma unroll
    for (int i = 0; i < 4; i++) {
        int slot = t + i * 256;
        int row = slot >> 3, seg = slot & 7;
        cp16(sm + row * 128 + ((seg ^ (row & 7)) << 4),
             ga + (size_t)row * KDIM + seg * 16);
    }
#pragma unroll
    for (int i = 0; i < 4; i++) {
        int slot = t + i * 256;
        int row = slot >> 3, seg = slot & 7;
        cp16(sm + BM * 128 + row * 128 + ((seg ^ (row & 7)) << 4),
             gb + (size_t)row * KDIM + seg * 16);
    }
}

// -------- dp4a 64B-chunk loader: permuted 512B-window layout, conflict-free --------
// seg s of row r lives at (r>>3)*512 + (s*8 + (r&7))*16
__device__ __forceinline__ void load_stage64(uint32_t sm, const char* gA, const char* gB,
                                             int koff, int t) {
#pragma unroll
    for (int i = 0; i < 2; i++) {
        int slot = t + i * 256;
        int row = slot >> 2, seg = slot & 3;
        uint32_t off = (uint32_t)((row >> 3) * 512 + ((seg * 8 + (row & 7)) << 4));
        cp16(sm + off, gA + (size_t)row * KDIM + koff + seg * 16);
    }
#pragma unroll
    for (int i = 0; i < 2; i++) {
        int slot = t + i * 256;
        int row = slot >> 2, seg = slot & 3;
        uint32_t off = (uint32_t)((row >> 3) * 512 + ((seg * 8 + (row & 7)) << 4));
        cp16(sm + 8192 + off, gB + (size_t)row * KDIM + koff + seg * 16);
    }
}

// ---- persistent hybrid GEMM: 512 threads, warps 0-7 IMMA, warps 8-15 dp4a ----
__global__ __launch_bounds__(512, 1)
void gemm_kernel(const float* __restrict__ bias, float* __restrict__ out) {
    extern __shared__ __align__(1024) char smem[];
    uint32_t sb = smem_u32(smem);
    int tid = threadIdx.x;
    int bid = blockIdx.x;
    int nt = (TILES_TOT - bid + GRID - 1) / GRID;   // tiles this CTA processes

    if (tid < 256) {
        // ========== IMMA group: pair-granular pipeline (4 buffers, bar every 2 chunks) ==========
        int lane = tid & 31, wid = tid >> 5;
        int warp_m = wid >> 1, warp_n = wid & 1;     // 4x2 warps, warp tile 32x64

        int tq = lane >> 3, r = lane & 7;
        int rowA[2], rowB[4];
#pragma unroll
        for (int im = 0; im < 2; im++) rowA[im] = warp_m * 32 + im * 16 + (tq & 1) * 8 + r;
        int segA = tq >> 1;
#pragma unroll
        for (int nb = 0; nb < 4; nb++) rowB[nb] = warp_n * 64 + nb * 16 + (tq >> 1) * 8 + r;
        int segB = tq & 1;

        int ld_tile = bid, ld_pair = 0;
        const char* lA = (const char*)g_A8 + (size_t)(ld_tile >> 5) * BM * KDIM;
        const char* lB = (const char*)g_B8 + (size_t)(ld_tile & 31) * BN * KDIM;

        // prologue: load pair 0 (chunks 0,1) into slot 0
        load_stage(sb + 0 * STAGE_BYTES, lA, lB, 0, tid);
        load_stage(sb + 1 * STAGE_BYTES, lA, lB, 1, tid);
        asm volatile("cp.async.commit_group;" ::: "memory");

        int P = 0;   // global pair counter; slot = P & 1

#pragma unroll 1
        for (int t = 0; t < nt; t++) {
            int T = bid + t * GRID;

            int c[2][8][4];
#pragma unroll
            for (int im = 0; im < 2; im++)
#pragma unroll
                for (int n8 = 0; n8 < 8; n8++)
#pragma unroll
                    for (int q = 0; q < 4; q++) c[im][n8][q] = 0;

#pragma unroll 1
            for (int p = 0; p < NPAIR; p++) {
                asm volatile("cp.async.wait_group 0;" ::: "memory");  // pair P resident
                asm volatile("bar.sync 1, 256;" ::: "memory");        // pair P-1 consumed

                // issue pair P+1 into the freed slot
                ld_pair++;
                if (ld_pair == NPAIR) {
                    ld_pair = 0;
                    ld_tile += GRID;
                    if (ld_tile < TILES_TOT) {
                        lA = (const char*)g_A8 + (size_t)(ld_tile >> 5) * BM * KDIM;
                        lB = (const char*)g_B8 + (size_t)(ld_tile & 31) * BN * KDIM;
                    }
                }
                if (ld_tile < TILES_TOT) {
                    uint32_t s0 = sb + (uint32_t)((((P + 1) & 1) * 2) * STAGE_BYTES);
                    load_stage(s0, lA, lB, ld_pair * 2, tid);
                    load_stage(s0 + STAGE_BYTES, lA, lB, ld_pair * 2 + 1, tid);
                }
                asm volatile("cp.async.commit_group;" ::: "memory");

                // compute both chunks of pair P (no barrier between them)
#pragma unroll
                for (int u = 0; u < 2; u++) {
                    uint32_t sA = sb + (uint32_t)((((P & 1) * 2) + u) * STAGE_BYTES);
                    uint32_t sB = sA + BM * 128;
#pragma unroll
                    for (int j = 0; j < 4; j++) {
                        uint32_t a[2][4];
#pragma unroll
                        for (int im = 0; im < 2; im++) {
                            int seg = 2 * j + segA;
                            ldsm4(a[im], sA + rowA[im] * 128 + ((seg ^ (rowA[im] & 7)) << 4));
                        }
                        uint32_t bfr[8][2];
#pragma unroll
                        for (int nb = 0; nb < 4; nb++) {
                            uint32_t r4[4];
                            int seg = 2 * j + segB;
                            ldsm4(r4, sB + rowB[nb] * 128 + ((seg ^ (rowB[nb] & 7)) << 4));
                            bfr[2 * nb][0] = r4[0]; bfr[2 * nb][1] = r4[1];
                            bfr[2 * nb + 1][0] = r4[2]; bfr[2 * nb + 1][1] = r4[3];
                        }
#pragma unroll
                        for (int im = 0; im < 2; im++)
#pragma unroll
                            for (int n8 = 0; n8 < 8; n8++)
                                imma(c[im][n8], a[im], bfr[n8]);
                    }
                }
                P++;
            }

            // ---- epilogue: wait for dp4a partials(t), merge, dequant, store ----
            asm volatile("bar.sync 3, 512;" ::: "memory");

            const int* part = (const int*)(smem + SM_PART);
            int rl = warp_m * 32 + (lane >> 2);
            int cl = warp_n * 64 + (lane & 3) * 2;
            int m0 = (T >> 5) * BM + rl;
            int n0 = (T & 31) * BN + cl;

#pragma unroll
            for (int im = 0; im < 2; im++) {
#pragma unroll
                for (int n8 = 0; n8 < 8; n8++) {
                    int col = n0 + n8 * 8;
                    int lc = cl + n8 * 8;
                    float2 sc = *reinterpret_cast<const float2*>(&g_sc[col]);
                    float2 bi = *reinterpret_cast<const float2*>(&bias[col]);
                    int r0l = rl + im * 16, r1l = r0l + 8;
                    int p00 = part[r0l * PART_STRIDE + lc];
                    int p01 = part[r0l * PART_STRIDE + lc + 1];
                    int p10 = part[r1l * PART_STRIDE + lc];
                    int p11 = part[r1l * PART_STRIDE + lc + 1];
                    int r0 = m0 + im * 16, r1 = r0 + 8;
                    float2 v0, v1;
                    v0.x = (float)(c[im][n8][0] + p00) * sc.x + bi.x;
                    v0.y = (float)(c[im][n8][1] + p01) * sc.y + bi.y;
                    v1.x = (float)(c[im][n8][2] + p10) * sc.x + bi.x;
                    v1.y = (float)(c[im][n8][3] + p11) * sc.y + bi.y;
                    *reinterpret_cast<float2*>(out + (size_t)r0 * NDIM + col) = v0;
                    *reinterpret_cast<float2*>(out + (size_t)r1 * NDIM + col) = v1;
                }
            }
            asm volatile("membar.cta;" ::: "memory");
            asm volatile("bar.arrive 4, 512;" ::: "memory"); // partials consumed
        }
    } else {
        // ========== dp4a group: 64B chunks, 2-stage continuous stream ==========
        int dt = tid - 256;
        int dl = dt & 31, dwid = dt >> 5;
        int wm = dwid >> 2, wn = dwid & 3;   // 2x4 warps, warp tile 64x32
        int tm = dl >> 2, tn = dl & 3;       // 8x4 threads, thread tile 8x8

        uint32_t dbase = sb + SM_DP;

        // per-thread B offsets within the permuted stage layout
        uint32_t bOff[8];
#pragma unroll
        for (int j = 0; j < 8; j++) {
            int n = wn * 32 + 4 * j + tn;
            bOff[j] = (uint32_t)((n >> 3) * 512 + ((n & 7) << 4));
        }
        uint32_t aBase0 = (uint32_t)(wm * 4096 + (tm << 4));

        int ld_tile = bid, ld_kt = 0;     // 64B-chunk index within tile
        const char* lA = (const char*)g_A8 + (size_t)(ld_tile >> 5) * BM * KDIM;
        const char* lB = (const char*)g_B8 + (size_t)(ld_tile & 31) * BN * KDIM;

        load_stage64(dbase, lA, lB, KI * BK + 0 * 64, dt);
        asm volatile("cp.async.commit_group;" ::: "memory");

        int g = 0;   // global 64B-chunk counter; buffer = g & 1

#pragma unroll 1
        for (int t = 0; t < nt; t++) {
            int cd[8][8];
#pragma unroll
            for (int i = 0; i < 8; i++)
#pragma unroll
                for (int j = 0; j < 8; j++) cd[i][j] = 0;

#pragma unroll 1
            for (int kt = 0; kt < ND64; kt++) {
                asm volatile("cp.async.wait_group 0;" ::: "memory");   // chunk g resident
                asm volatile("bar.sync 2, 256;" ::: "memory");         // chunk g-1 consumed

                ld_kt++;
                if (ld_kt == ND64) {
                    ld_kt = 0;
                    ld_tile += GRID;
                    if (ld_tile < TILES_TOT) {
                        lA = (const char*)g_A8 + (size_t)(ld_tile >> 5) * BM * KDIM;
                        lB = (const char*)g_B8 + (size_t)(ld_tile & 31) * BN * KDIM;
                    }
                }
                if (ld_tile < TILES_TOT)
                    load_stage64(dbase + (uint32_t)(((g + 1) & 1) * DP_STAGE), lA, lB,
                                 KI * BK + ld_kt * 64, dt);
                asm volatile("cp.async.commit_group;" ::: "memory");

                uint32_t sA = dbase + (uint32_t)((g & 1) * DP_STAGE);
                uint32_t sB = sA + 8192;
                uint32_t aB = sA + aBase0;

#pragma unroll
                for (int seg = 0; seg < 4; seg++) {
                    uint32_t segoff = (uint32_t)(seg << 7);   // seg*128

                    uint32_t a[8][4];
#pragma unroll
                    for (int i = 0; i < 8; i++)
                        lds128(a[i], aB + i * 512 + segoff);

#pragma unroll
                    for (int jh = 0; jh < 2; jh++) {
                        uint32_t b[4][4];
#pragma unroll
                        for (int jj = 0; jj < 4; jj++)
                            lds128(b[jj], sB + bOff[jh * 4 + jj] + segoff);
#pragma unroll
                        for (int i = 0; i < 8; i++)
#pragma unroll
                            for (int jj = 0; jj < 4; jj++) {
                                int& acc = cd[i][jh * 4 + jj];
                                dp4a_acc(acc, a[i][0], b[jj][0]);
                                dp4a_acc(acc, a[i][1], b[jj][1]);
                                dp4a_acc(acc, a[i][2], b[jj][2]);
                                dp4a_acc(acc, a[i][3], b[jj][3]);
                            }
                    }
                }
                g++;
            }

            // wait until epilogue(t-1) consumed the partial buffer
            if (t > 0)
                asm volatile("bar.sync 4, 512;" ::: "memory");

            int* part = (int*)(smem + SM_PART);
            int prow = wm * 64 + tm, pcol = wn * 32 + tn;
#pragma unroll
            for (int i = 0; i < 8; i++)
#pragma unroll
                for (int j = 0; j < 8; j++)
                    part[(prow + 8 * i) * PART_STRIDE + pcol + 4 * j] = cd[i][j];

            asm volatile("membar.cta;" ::: "memory");
            asm volatile("bar.arrive 3, 512;" ::: "memory");  // partials(t) ready
        }
    }
}

// -------- launch --------
extern "C" void kernel_launch(void* const* d_in, const int* in_sizes, int n_in,
                              void* d_out, int out_size) {
    const float* x        = (const float*)d_in[0];
    const float* in_scale = (const float*)d_in[1];
    const float* act      = (const float*)d_in[2];
    const int*   w        = (const int*)d_in[3];
    const float* w_scale  = (const float*)d_in[4];
    const float* bias     = (const float*)d_in[5];
    float* out = (float*)d_out;

    int M = in_sizes[0] / KDIM;  // 8192

    cudaFuncSetAttribute(gemm_kernel, cudaFuncAttributeMaxDynamicSharedMemorySize, SMEM_TOTAL);

    precomp_scales<<<(KDIM + 255) / 256, 256>>>(in_scale, act, w_scale);

    int xa4 = (M * KDIM) / 4;
    quant_x<<<(xa4 + 255) / 256, 256>>>(x, xa4);

    int wb4 = (NDIM * KDIM) / 4;
    conv_w<<<(wb4 + 255) / 256, 256>>>(w, wb4);

    gemm_kernel<<<GRID, 512, SMEM_TOTAL>>>(bias, out);
}

// round 10
// speedup vs baseline: 1.1010x; 1.1010x over previous
#include <cuda_runtime.h>
#include <cuda_bf16.h>
#include <cstdint>
#include <cstddef>

// Fixed problem dims: B=4, S=2048 -> M=8192, K=4096, N=4096
#define KDIM 4096
#define NDIM 4096
#define MMAX 8192

#define BM 128
#define BN 128
#define BK 128
#define KT (KDIM / BK)      // 32 k-chunks
#define KI 19               // k-chunks done by IMMA warps [0, KI)
#define KD (KT - KI)        // k-chunks done by dp4a warps

#define TILES_TOT ((MMAX / BM) * (NDIM / BN))  // 2048
#define GRID 148                                // persistent CTAs (1/SM)

#define STAGE_BYTES (BM * BK + BN * BK)        // 32768
#define IMMA_STAGES 3
#define DP_STAGES 2
#define SM_DP   (IMMA_STAGES * STAGE_BYTES)            // 98304
#define SM_PART (SM_DP + DP_STAGES * STAGE_BYTES)      // 163840
#define PART_STRIDE 132                                 // padded int32 row stride
#define SMEM_TOTAL (SM_PART + BM * PART_STRIDE * 4)    // 231424

// -------- device scratch --------
__device__ int8_t g_A8[(size_t)MMAX * KDIM];
__device__ int8_t g_B8[(size_t)NDIM * KDIM];
__device__ float  g_comb[KDIM];
__device__ float  g_sc[NDIM];

// -------- helpers --------
__device__ __forceinline__ uint32_t smem_u32(const void* p) {
    uint32_t a;
    asm("{ .reg .u64 t; cvta.to.shared.u64 t, %1; cvt.u32.u64 %0, t; }" : "=r"(a) : "l"(p));
    return a;
}
__device__ __forceinline__ void cp16(uint32_t s, const void* g) {
    asm volatile("cp.async.cg.shared.global [%0], [%1], 16;" :: "r"(s), "l"(g));
}
__device__ __forceinline__ void ldsm4(uint32_t* d, uint32_t addr) {
    asm volatile("ldmatrix.sync.aligned.m8n8.x4.shared.b16 {%0,%1,%2,%3}, [%4];"
                 : "=r"(d[0]), "=r"(d[1]), "=r"(d[2]), "=r"(d[3]) : "r"(addr));
}
__device__ __forceinline__ void imma(int* c, const uint32_t* a, const uint32_t* b) {
    asm volatile(
        "mma.sync.aligned.m16n8k32.row.col.s32.s8.s8.s32 "
        "{%0,%1,%2,%3}, {%4,%5,%6,%7}, {%8,%9}, {%0,%1,%2,%3};"
        : "+r"(c[0]), "+r"(c[1]), "+r"(c[2]), "+r"(c[3])
        : "r"(a[0]), "r"(a[1]), "r"(a[2]), "r"(a[3]), "r"(b[0]), "r"(b[1]));
}
__device__ __forceinline__ void dp4a_acc(int& c, uint32_t a, uint32_t b) {
    asm volatile("dp4a.s32.s32 %0, %1, %2, %0;" : "+r"(c) : "r"(a), "r"(b));
}
__device__ __forceinline__ void lds128(uint32_t* d, uint32_t addr) {
    asm volatile("ld.shared.v4.b32 {%0,%1,%2,%3}, [%4];"
                 : "=r"(d[0]), "=r"(d[1]), "=r"(d[2]), "=r"(d[3]) : "r"(addr));
}

// -------- preprocessing --------
__global__ void precomp_scales(const float* __restrict__ in_scale,
                               const float* __restrict__ act,
                               const float* __restrict__ w_scale) {
    int i = blockIdx.x * blockDim.x + threadIdx.x;
    float a = act[0];
    if (i < KDIM) g_comb[i] = __fdiv_rn(in_scale[i], a);
    if (i < NDIM) g_sc[i] = a * w_scale[i];
}

__global__ void quant_x(const float* __restrict__ x, int total4) {
    int i = blockIdx.x * blockDim.x + threadIdx.x;
    if (i >= total4) return;
    float4 v = reinterpret_cast<const float4*>(x)[i];
    int col = (i & (KDIM / 4 - 1)) * 4;
    int q0 = min(max(__float2int_rn(v.x * g_comb[col + 0]), -127), 127);
    int q1 = min(max(__float2int_rn(v.y * g_comb[col + 1]), -127), 127);
    int q2 = min(max(__float2int_rn(v.z * g_comb[col + 2]), -127), 127);
    int q3 = min(max(__float2int_rn(v.w * g_comb[col + 3]), -127), 127);
    uint32_t p = (uint32_t)(q0 & 0xFF) | ((uint32_t)(q1 & 0xFF) << 8) |
                 ((uint32_t)(q2 & 0xFF) << 16) | ((uint32_t)(q3 & 0xFF) << 24);
    reinterpret_cast<uint32_t*>(g_A8)[i] = p;
}

__global__ void conv_w(const int* __restrict__ w, int total4) {
    int i = blockIdx.x * blockDim.x + threadIdx.x;
    if (i >= total4) return;
    int4 v = reinterpret_cast<const int4*>(w)[i];
    uint32_t p = (uint32_t)(v.x & 0xFF) | ((uint32_t)(v.y & 0xFF) << 8) |
                 ((uint32_t)(v.z & 0xFF) << 16) | ((uint32_t)(v.w & 0xFF) << 24);
    reinterpret_cast<uint32_t*>(g_B8)[i] = p;
}

// -------- shared tile loader (A then B, XOR-swizzled, 256 threads) --------
__device__ __forceinline__ void load_stage(uint32_t sm, const char* gA, const char* gB,
                                           int kt, int t) {
    const char* ga = gA + (size_t)kt * BK;
    const char* gb = gB + (size_t)kt * BK;
#pragma unroll
    for (int i = 0; i < 4; i++) {
        int slot = t + i * 256;
        int row = slot >> 3, seg = slot & 7;
        cp16(sm + row * 128 + ((seg ^ (row & 7)) << 4),
             ga + (size_t)row * KDIM + seg * 16);
    }
#pragma unroll
    for (int i = 0; i < 4; i++) {
        int slot = t + i * 256;
        int row = slot >> 3, seg = slot & 7;
        cp16(sm + BM * 128 + row * 128 + ((seg ^ (row & 7)) << 4),
             gb + (size_t)row * KDIM + seg * 16);
    }
}

// ---- persistent hybrid GEMM: warps 0-7 IMMA (+dump), warps 8-15 dp4a (+epilogue) ----
__global__ __launch_bounds__(512, 1)
void gemm_kernel(const float* __restrict__ bias, float* __restrict__ out) {
    extern __shared__ __align__(1024) char smem[];
    uint32_t sb = smem_u32(smem);
    int tid = threadIdx.x;
    int bid = blockIdx.x;
    int nt = (TILES_TOT - bid + GRID - 1) / GRID;   // tiles this CTA processes

    if (tid < 256) {
        // ========== IMMA group: continuous chunk stream + partial dump ==========
        int lane = tid & 31, wid = tid >> 5;
        int warp_m = wid >> 1, warp_n = wid & 1;     // 4x2 warps, warp tile 32x64

        int tq = lane >> 3, r = lane & 7;
        int rowA[2], rowB[4];
#pragma unroll
        for (int im = 0; im < 2; im++) rowA[im] = warp_m * 32 + im * 16 + (tq & 1) * 8 + r;
        int segA = tq >> 1;
#pragma unroll
        for (int nb = 0; nb < 4; nb++) rowB[nb] = warp_n * 64 + nb * 16 + (tq >> 1) * 8 + r;
        int segB = tq & 1;

        int rl = warp_m * 32 + (lane >> 2);
        int cl = warp_n * 64 + (lane & 3) * 2;

        int ld_tile = bid, ld_kt = 0;
        const char* lA = (const char*)g_A8 + (size_t)(ld_tile >> 5) * BM * KDIM;
        const char* lB = (const char*)g_B8 + (size_t)(ld_tile & 31) * BN * KDIM;

        load_stage(sb + 0 * STAGE_BYTES, lA, lB, 0, tid);
        asm volatile("cp.async.commit_group;" ::: "memory");
        ld_kt = 1;
        load_stage(sb + 1 * STAGE_BYTES, lA, lB, 1, tid);
        asm volatile("cp.async.commit_group;" ::: "memory");

        int g = 0;   // global chunk counter; stage = g % 3

#pragma unroll 1
        for (int t = 0; t < nt; t++) {
            int c[2][8][4];
#pragma unroll
            for (int im = 0; im < 2; im++)
#pragma unroll
                for (int n8 = 0; n8 < 8; n8++)
#pragma unroll
                    for (int q = 0; q < 4; q++) c[im][n8][q] = 0;

#pragma unroll 1
            for (int kt = 0; kt < KI; kt++) {
                asm volatile("cp.async.wait_group 1;" ::: "memory");
                asm volatile("bar.sync 1, 256;" ::: "memory");

                ld_kt++;
                if (ld_kt == KI) {
                    ld_kt = 0;
                    ld_tile += GRID;
                    if (ld_tile < TILES_TOT) {
                        lA = (const char*)g_A8 + (size_t)(ld_tile >> 5) * BM * KDIM;
                        lB = (const char*)g_B8 + (size_t)(ld_tile & 31) * BN * KDIM;
                    }
                }
                if (ld_tile < TILES_TOT)
                    load_stage(sb + (uint32_t)(((g + 2) % 3) * STAGE_BYTES), lA, lB, ld_kt, tid);
                asm volatile("cp.async.commit_group;" ::: "memory");

                uint32_t sA = sb + (uint32_t)((g % 3) * STAGE_BYTES);
                uint32_t sB = sA + BM * 128;

#pragma unroll
                for (int j = 0; j < 4; j++) {
                    uint32_t a[2][4];
#pragma unroll
                    for (int im = 0; im < 2; im++) {
                        int seg = 2 * j + segA;
                        ldsm4(a[im], sA + rowA[im] * 128 + ((seg ^ (rowA[im] & 7)) << 4));
                    }
                    uint32_t bfr[8][2];
#pragma unroll
                    for (int nb = 0; nb < 4; nb++) {
                        uint32_t r4[4];
                        int seg = 2 * j + segB;
                        ldsm4(r4, sB + rowB[nb] * 128 + ((seg ^ (rowB[nb] & 7)) << 4));
                        bfr[2 * nb][0] = r4[0]; bfr[2 * nb][1] = r4[1];
                        bfr[2 * nb + 1][0] = r4[2]; bfr[2 * nb + 1][1] = r4[3];
                    }
#pragma unroll
                    for (int im = 0; im < 2; im++)
#pragma unroll
                        for (int n8 = 0; n8 < 8; n8++)
                            imma(c[im][n8], a[im], bfr[n8]);
                }
                g++;
            }

            // ---- dump accumulators to smem; dp4a warps do the merge/store ----
            if (t > 0)
                asm volatile("bar.sync 4, 512;" ::: "memory");   // epilogue(t-1) done

            int* part = (int*)(smem + SM_PART);
#pragma unroll
            for (int im = 0; im < 2; im++) {
#pragma unroll
                for (int n8 = 0; n8 < 8; n8++) {
                    int lc = cl + n8 * 8;
                    int r0l = rl + im * 16, r1l = r0l + 8;
                    *reinterpret_cast<int2*>(&part[r0l * PART_STRIDE + lc]) =
                        make_int2(c[im][n8][0], c[im][n8][1]);
                    *reinterpret_cast<int2*>(&part[r1l * PART_STRIDE + lc]) =
                        make_int2(c[im][n8][2], c[im][n8][3]);
                }
            }
            asm volatile("membar.cta;" ::: "memory");
            asm volatile("bar.arrive 3, 512;" ::: "memory");   // partials(t) ready
        }
    } else {
        // ========== dp4a group: continuous 2-stage stream + merged epilogue ==========
        int dt = tid - 256;
        int dl = dt & 31, dwid = dt >> 5;
        int wm = dwid >> 2, wn = dwid & 3;   // 2x4 warps, warp tile 64x32
        int tm = dl >> 2, tn = dl & 3;       // 8x4 threads, thread tile 8x8

        uint32_t dbase = sb + SM_DP;

        int ld_tile = bid, ld_kt = 0;
        const char* lA = (const char*)g_A8 + (size_t)(ld_tile >> 5) * BM * KDIM;
        const char* lB = (const char*)g_B8 + (size_t)(ld_tile & 31) * BN * KDIM;

        load_stage(dbase + 0 * STAGE_BYTES, lA, lB, KI + 0, dt);
        asm volatile("cp.async.commit_group;" ::: "memory");

        int g = 0;   // global chunk counter; buffer = g & 1

#pragma unroll 1
        for (int t = 0; t < nt; t++) {
            int T = bid + t * GRID;

            int cd[8][8];
#pragma unroll
            for (int i = 0; i < 8; i++)
#pragma unroll
                for (int j = 0; j < 8; j++) cd[i][j] = 0;

#pragma unroll 1
            for (int kt = 0; kt < KD; kt++) {
                asm volatile("cp.async.wait_group 0;" ::: "memory");   // chunk g resident
                asm volatile("bar.sync 2, 256;" ::: "memory");         // chunk g-1 consumed

                ld_kt++;
                if (ld_kt == KD) {
                    ld_kt = 0;
                    ld_tile += GRID;
                    if (ld_tile < TILES_TOT) {
                        lA = (const char*)g_A8 + (size_t)(ld_tile >> 5) * BM * KDIM;
                        lB = (const char*)g_B8 + (size_t)(ld_tile & 31) * BN * KDIM;
                    }
                }
                if (ld_tile < TILES_TOT)
                    load_stage(dbase + (uint32_t)(((g + 1) & 1) * STAGE_BYTES), lA, lB,
                               KI + ld_kt, dt);
                asm volatile("cp.async.commit_group;" ::: "memory");

                uint32_t sA = dbase + (uint32_t)((g & 1) * STAGE_BYTES);
                uint32_t sB = sA + BM * 128;

                uint32_t aA = sA + (uint32_t)((wm * 64 + tm) * 128 + (tm << 4));
                uint32_t bE = sB + (uint32_t)((wn * 32 + tn) * 128 + (tn << 4));
                uint32_t bO = bE + 512 + 64;

#pragma unroll 1
                for (int seg = 0; seg < 8; seg++) {
                    uint32_t as  = aA ^ (uint32_t)(seg << 4);
                    uint32_t bsE = bE ^ (uint32_t)(seg << 4);
                    uint32_t bsO = bO ^ (uint32_t)(seg << 4);

                    uint32_t a[8][4];
#pragma unroll
                    for (int i = 0; i < 8; i++)
                        lds128(a[i], as + i * 1024);

#pragma unroll
                    for (int jh = 0; jh < 2; jh++) {
                        uint32_t b[4][4];
#pragma unroll
                        for (int jj = 0; jj < 4; jj++) {
                            int j = jh * 4 + jj;
                            uint32_t base = (j & 1) ? bsO : bsE;
                            lds128(b[jj], base + (j >> 1) * 1024);
                        }
#pragma unroll
                        for (int i = 0; i < 8; i++)
#pragma unroll
                            for (int jj = 0; jj < 4; jj++) {
                                int& acc = cd[i][jh * 4 + jj];
                                dp4a_acc(acc, a[i][0], b[jj][0]);
                                dp4a_acc(acc, a[i][1], b[jj][1]);
                                dp4a_acc(acc, a[i][2], b[jj][2]);
                                dp4a_acc(acc, a[i][3], b[jj][3]);
                            }
                    }
                }
                g++;
            }

            // ---- merged epilogue on dp4a warps ----
            int n0g = (T & 31) * BN + wn * 32 + tn;
            float scv[8], biv[8];
#pragma unroll
            for (int j = 0; j < 8; j++) {
                scv[j] = g_sc[n0g + 4 * j];
                biv[j] = bias[n0g + 4 * j];
            }

            asm volatile("bar.sync 3, 512;" ::: "memory");   // partials(t) ready

            const int* part = (const int*)(smem + SM_PART);
            int prow = wm * 64 + tm;
            int pcol = wn * 32 + tn;
            int m0 = (T >> 5) * BM + prow;

#pragma unroll
            for (int i = 0; i < 8; i++) {
                float* orow = out + (size_t)(m0 + 8 * i) * NDIM + n0g;
                const int* prw = part + (prow + 8 * i) * PART_STRIDE + pcol;
#pragma unroll
                for (int j = 0; j < 8; j++)
                    orow[4 * j] = (float)(cd[i][j] + prw[4 * j]) * scv[j] + biv[j];
            }
            asm volatile("membar.cta;" ::: "memory");
            asm volatile("bar.arrive 4, 512;" ::: "memory"); // partials consumed
        }
    }
}

// -------- launch --------
extern "C" void kernel_launch(void* const* d_in, const int* in_sizes, int n_in,
                              void* d_out, int out_size) {
    const float* x        = (const float*)d_in[0];
    const float* in_scale = (const float*)d_in[1];
    const float* act      = (const float*)d_in[2];
    const int*   w        = (const int*)d_in[3];
    const float* w_scale  = (const float*)d_in[4];
    const float* bias     = (const float*)d_in[5];
    float* out = (float*)d_out;

    int M = in_sizes[0] / KDIM;  // 8192

    cudaFuncSetAttribute(gemm_kernel, cudaFuncAttributeMaxDynamicSharedMemorySize, SMEM_TOTAL);

    precomp_scales<<<(KDIM + 255) / 256, 256>>>(in_scale, act, w_scale);

    int xa4 = (M * KDIM) / 4;
    quant_x<<<(xa4 + 255) / 256, 256>>>(x, xa4);

    int wb4 = (NDIM * KDIM) / 4;
    conv_w<<<(wb4 + 255) / 256, 256>>>(w, wb4);

    gemm_kernel<<<GRID, 512, SMEM_TOTAL>>>(bias, out);
}

// round 11
// speedup vs baseline: 1.1351x; 1.0309x over previous
#include <cuda_runtime.h>
#include <cuda_bf16.h>
#include <cstdint>
#include <cstddef>

// Fixed problem dims: B=4, S=2048 -> M=8192, K=4096, N=4096
#define KDIM 4096
#define NDIM 4096
#define MMAX 8192

#define BM 128
#define BN 128
#define BK 128
#define KT (KDIM / BK)      // 32 k-chunks
#define KI 18               // k-chunks done by IMMA warps (even)
#define KD (KT - KI)        // 14 k-chunks done by dp4a warps
#define NPAIR (KI / 2)      // 9 IMMA chunk-pairs

#define TILES_TOT ((MMAX / BM) * (NDIM / BN))  // 2048
#define GRID 148                                // persistent CTAs (1/SM)

#define STAGE_BYTES (BM * BK + BN * BK)        // 32768
#define SM_DP   (4 * STAGE_BYTES)               // 131072 (IMMA: 4 buffers = 2 pairs)
#define SM_PART (SM_DP + 2 * STAGE_BYTES)       // 196608 (dp4a: 2 buffers)
#define PART_STRIDE 132                         // padded int32 row stride
#define PART_ROWS 64                            // half-tile partial buffer
#define SMEM_TOTAL (SM_PART + PART_ROWS * PART_STRIDE * 4)  // 230400

// -------- device scratch --------
__device__ int8_t g_A8[(size_t)MMAX * KDIM];
__device__ int8_t g_B8[(size_t)NDIM * KDIM];
__device__ float  g_comb[KDIM];
__device__ float  g_sc[NDIM];

// -------- helpers --------
__device__ __forceinline__ uint32_t smem_u32(const void* p) {
    uint32_t a;
    asm("{ .reg .u64 t; cvta.to.shared.u64 t, %1; cvt.u32.u64 %0, t; }" : "=r"(a) : "l"(p));
    return a;
}
__device__ __forceinline__ void cp16(uint32_t s, const void* g) {
    asm volatile("cp.async.cg.shared.global [%0], [%1], 16;" :: "r"(s), "l"(g));
}
__device__ __forceinline__ void ldsm4(uint32_t* d, uint32_t addr) {
    asm volatile("ldmatrix.sync.aligned.m8n8.x4.shared.b16 {%0,%1,%2,%3}, [%4];"
                 : "=r"(d[0]), "=r"(d[1]), "=r"(d[2]), "=r"(d[3]) : "r"(addr));
}
__device__ __forceinline__ void imma(int* c, const uint32_t* a, const uint32_t* b) {
    asm volatile(
        "mma.sync.aligned.m16n8k32.row.col.s32.s8.s8.s32 "
        "{%0,%1,%2,%3}, {%4,%5,%6,%7}, {%8,%9}, {%0,%1,%2,%3};"
        : "+r"(c[0]), "+r"(c[1]), "+r"(c[2]), "+r"(c[3])
        : "r"(a[0]), "r"(a[1]), "r"(a[2]), "r"(a[3]), "r"(b[0]), "r"(b[1]));
}
__device__ __forceinline__ void dp4a_acc(int& c, uint32_t a, uint32_t b) {
    asm volatile("dp4a.s32.s32 %0, %1, %2, %0;" : "+r"(c) : "r"(a), "r"(b));
}
__device__ __forceinline__ void lds128(uint32_t* d, uint32_t addr) {
    asm volatile("ld.shared.v4.b32 {%0,%1,%2,%3}, [%4];"
                 : "=r"(d[0]), "=r"(d[1]), "=r"(d[2]), "=r"(d[3]) : "r"(addr));
}

// -------- preprocessing --------
__global__ void precomp_scales(const float* __restrict__ in_scale,
                               const float* __restrict__ act,
                               const float* __restrict__ w_scale) {
    int i = blockIdx.x * blockDim.x + threadIdx.x;
    float a = act[0];
    if (i < KDIM) g_comb[i] = __fdiv_rn(in_scale[i], a);
    if (i < NDIM) g_sc[i] = a * w_scale[i];
}

__global__ void quant_x(const float* __restrict__ x, int total4) {
    int i = blockIdx.x * blockDim.x + threadIdx.x;
    if (i >= total4) return;
    float4 v = reinterpret_cast<const float4*>(x)[i];
    int col = (i & (KDIM / 4 - 1)) * 4;
    int q0 = min(max(__float2int_rn(v.x * g_comb[col + 0]), -127), 127);
    int q1 = min(max(__float2int_rn(v.y * g_comb[col + 1]), -127), 127);
    int q2 = min(max(__float2int_rn(v.z * g_comb[col + 2]), -127), 127);
    int q3 = min(max(__float2int_rn(v.w * g_comb[col + 3]), -127), 127);
    uint32_t p = (uint32_t)(q0 & 0xFF) | ((uint32_t)(q1 & 0xFF) << 8) |
                 ((uint32_t)(q2 & 0xFF) << 16) | ((uint32_t)(q3 & 0xFF) << 24);
    reinterpret_cast<uint32_t*>(g_A8)[i] = p;
}

__global__ void conv_w(const int* __restrict__ w, int total4) {
    int i = blockIdx.x * blockDim.x + threadIdx.x;
    if (i >= total4) return;
    int4 v = reinterpret_cast<const int4*>(w)[i];
    uint32_t p = (uint32_t)(v.x & 0xFF) | ((uint32_t)(v.y & 0xFF) << 8) |
                 ((uint32_t)(v.z & 0xFF) << 16) | ((uint32_t)(v.w & 0xFF) << 24);
    reinterpret_cast<uint32_t*>(g_B8)[i] = p;
}

// -------- shared tile loader (A then B, XOR-swizzled, 256 threads) --------
__device__ __forceinline__ void load_stage(uint32_t sm, const char* gA, const char* gB,
                                           int kt, int t) {
    const char* ga = gA + (size_t)kt * BK;
    const char* gb = gB + (size_t)kt * BK;
#pragma unroll
    for (int i = 0; i < 4; i++) {
        int slot = t + i * 256;
        int row = slot >> 3, seg = slot & 7;
        cp16(sm + row * 128 + ((seg ^ (row & 7)) << 4),
             ga + (size_t)row * KDIM + seg * 16);
    }
#pragma unroll
    for (int i = 0; i < 4; i++) {
        int slot = t + i * 256;
        int row = slot >> 3, seg = slot & 7;
        cp16(sm + BM * 128 + row * 128 + ((seg ^ (row & 7)) << 4),
             gb + (size_t)row * KDIM + seg * 16);
    }
}

// ---- persistent hybrid GEMM: warps 0-7 IMMA (pair-granular), warps 8-15 dp4a ----
__global__ __launch_bounds__(512, 1)
void gemm_kernel(const float* __restrict__ bias, float* __restrict__ out) {
    extern __shared__ __align__(1024) char smem[];
    uint32_t sb = smem_u32(smem);
    int tid = threadIdx.x;
    int bid = blockIdx.x;
    int nt = (TILES_TOT - bid + GRID - 1) / GRID;   // tiles this CTA processes

    if (tid < 256) {
        // ===== IMMA group: 2-pair pipeline, one barrier per 2 chunks =====
        int lane = tid & 31, wid = tid >> 5;
        int warp_m = wid >> 1, warp_n = wid & 1;     // 4x2 warps, warp tile 32x64

        int tq = lane >> 3, r = lane & 7;
        int rowA[2], rowB[4];
#pragma unroll
        for (int im = 0; im < 2; im++) rowA[im] = warp_m * 32 + im * 16 + (tq & 1) * 8 + r;
        int segA = tq >> 1;
#pragma unroll
        for (int nb = 0; nb < 4; nb++) rowB[nb] = warp_n * 64 + nb * 16 + (tq >> 1) * 8 + r;
        int segB = tq & 1;

        int pidx0 = warp_m * 16 + (lane >> 2);       // partial-buffer row (both phases)
        int cl = warp_n * 64 + (lane & 3) * 2;

        int ld_tile = bid, ld_pair = 0;
        const char* lA = (const char*)g_A8 + (size_t)(ld_tile >> 5) * BM * KDIM;
        const char* lB = (const char*)g_B8 + (size_t)(ld_tile & 31) * BN * KDIM;

        // prologue: pair 0 into slots 0,1
        load_stage(sb + 0 * STAGE_BYTES, lA, lB, 0, tid);
        load_stage(sb + 1 * STAGE_BYTES, lA, lB, 1, tid);
        asm volatile("cp.async.commit_group;" ::: "memory");

        int P = 0;   // global pair counter; slot-pair = P & 1

#pragma unroll 1
        for (int t = 0; t < nt; t++) {
            int c[2][8][4];
#pragma unroll
            for (int im = 0; im < 2; im++)
#pragma unroll
                for (int n8 = 0; n8 < 8; n8++)
#pragma unroll
                    for (int q = 0; q < 4; q++) c[im][n8][q] = 0;

#pragma unroll 1
            for (int p = 0; p < NPAIR; p++) {
                asm volatile("bar.sync 1, 256;" ::: "memory");   // pair P-1 buffers free

                // issue pair P+1 into the freed slot-pair
                ld_pair++;
                if (ld_pair == NPAIR) {
                    ld_pair = 0;
                    ld_tile += GRID;
                    if (ld_tile < TILES_TOT) {
                        lA = (const char*)g_A8 + (size_t)(ld_tile >> 5) * BM * KDIM;
                        lB = (const char*)g_B8 + (size_t)(ld_tile & 31) * BN * KDIM;
                    }
                }
                if (ld_tile < TILES_TOT) {
                    uint32_t s0 = sb + (uint32_t)((((P + 1) & 1) * 2) * STAGE_BYTES);
                    load_stage(s0, lA, lB, ld_pair * 2, tid);
                    load_stage(s0 + STAGE_BYTES, lA, lB, ld_pair * 2 + 1, tid);
                }
                asm volatile("cp.async.commit_group;" ::: "memory");
                asm volatile("cp.async.wait_group 1;" ::: "memory");  // pair P resident

                // compute both chunks of pair P, no barrier between
#pragma unroll
                for (int u = 0; u < 2; u++) {
                    uint32_t sA = sb + (uint32_t)((((P & 1) * 2) + u) * STAGE_BYTES);
                    uint32_t sB = sA + BM * 128;
#pragma unroll
                    for (int j = 0; j < 4; j++) {
                        uint32_t a[2][4];
#pragma unroll
                        for (int im = 0; im < 2; im++) {
                            int seg = 2 * j + segA;
                            ldsm4(a[im], sA + rowA[im] * 128 + ((seg ^ (rowA[im] & 7)) << 4));
                        }
                        uint32_t bfr[8][2];
#pragma unroll
                        for (int nb = 0; nb < 4; nb++) {
                            uint32_t r4[4];
                            int seg = 2 * j + segB;
                            ldsm4(r4, sB + rowB[nb] * 128 + ((seg ^ (rowB[nb] & 7)) << 4));
                            bfr[2 * nb][0] = r4[0]; bfr[2 * nb][1] = r4[1];
                            bfr[2 * nb + 1][0] = r4[2]; bfr[2 * nb + 1][1] = r4[3];
                        }
#pragma unroll
                        for (int im = 0; im < 2; im++)
#pragma unroll
                            for (int n8 = 0; n8 < 8; n8++)
                                imma(c[im][n8], a[im], bfr[n8]);
                    }
                }
                P++;
            }

            // ---- two-phase dump: im=0 then im=1 into the 64-row partial buffer ----
            int* part = (int*)(smem + SM_PART);
            if (t > 0)
                asm volatile("bar.sync 4, 512;" ::: "memory");   // phase B of t-1 consumed
#pragma unroll
            for (int n8 = 0; n8 < 8; n8++) {
                int lc = cl + n8 * 8;
                *reinterpret_cast<int2*>(&part[pidx0 * PART_STRIDE + lc]) =
                    make_int2(c[0][n8][0], c[0][n8][1]);
                *reinterpret_cast<int2*>(&part[(pidx0 + 8) * PART_STRIDE + lc]) =
                    make_int2(c[0][n8][2], c[0][n8][3]);
            }
            asm volatile("membar.cta;" ::: "memory");
            asm volatile("bar.arrive 3, 512;" ::: "memory");     // phase A ready

            asm volatile("bar.sync 4, 512;" ::: "memory");       // phase A consumed
#pragma unroll
            for (int n8 = 0; n8 < 8; n8++) {
                int lc = cl + n8 * 8;
                *reinterpret_cast<int2*>(&part[pidx0 * PART_STRIDE + lc]) =
                    make_int2(c[1][n8][0], c[1][n8][1]);
                *reinterpret_cast<int2*>(&part[(pidx0 + 8) * PART_STRIDE + lc]) =
                    make_int2(c[1][n8][2], c[1][n8][3]);
            }
            asm volatile("membar.cta;" ::: "memory");
            asm volatile("bar.arrive 3, 512;" ::: "memory");     // phase B ready
        }
    } else {
        // ===== dp4a group: unchanged R10 stream + two-phase merged epilogue =====
        int dt = tid - 256;
        int dl = dt & 31, dwid = dt >> 5;
        int wm = dwid >> 2, wn = dwid & 3;   // 2x4 warps, warp tile 64x32
        int tm = dl >> 2, tn = dl & 3;       // 8x4 threads, thread tile 8x8

        uint32_t dbase = sb + SM_DP;

        int ld_tile = bid, ld_kt = 0;
        const char* lA = (const char*)g_A8 + (size_t)(ld_tile >> 5) * BM * KDIM;
        const char* lB = (const char*)g_B8 + (size_t)(ld_tile & 31) * BN * KDIM;

        load_stage(dbase + 0 * STAGE_BYTES, lA, lB, KI + 0, dt);
        asm volatile("cp.async.commit_group;" ::: "memory");

        int g = 0;   // global chunk counter; buffer = g & 1

#pragma unroll 1
        for (int t = 0; t < nt; t++) {
            int T = bid + t * GRID;

            int cd[8][8];
#pragma unroll
            for (int i = 0; i < 8; i++)
#pragma unroll
                for (int j = 0; j < 8; j++) cd[i][j] = 0;

#pragma unroll 1
            for (int kt = 0; kt < KD; kt++) {
                asm volatile("cp.async.wait_group 0;" ::: "memory");
                asm volatile("bar.sync 2, 256;" ::: "memory");

                ld_kt++;
                if (ld_kt == KD) {
                    ld_kt = 0;
                    ld_tile += GRID;
                    if (ld_tile < TILES_TOT) {
                        lA = (const char*)g_A8 + (size_t)(ld_tile >> 5) * BM * KDIM;
                        lB = (const char*)g_B8 + (size_t)(ld_tile & 31) * BN * KDIM;
                    }
                }
                if (ld_tile < TILES_TOT)
                    load_stage(dbase + (uint32_t)(((g + 1) & 1) * STAGE_BYTES), lA, lB,
                               KI + ld_kt, dt);
                asm volatile("cp.async.commit_group;" ::: "memory");

                uint32_t sA = dbase + (uint32_t)((g & 1) * STAGE_BYTES);
                uint32_t sB = sA + BM * 128;

                uint32_t aA = sA + (uint32_t)((wm * 64 + tm) * 128 + (tm << 4));
                uint32_t bE = sB + (uint32_t)((wn * 32 + tn) * 128 + (tn << 4));
                uint32_t bO = bE + 512 + 64;

#pragma unroll 1
                for (int seg = 0; seg < 8; seg++) {
                    uint32_t as  = aA ^ (uint32_t)(seg << 4);
                    uint32_t bsE = bE ^ (uint32_t)(seg << 4);
                    uint32_t bsO = bO ^ (uint32_t)(seg << 4);

                    uint32_t a[8][4];
#pragma unroll
                    for (int i = 0; i < 8; i++)
                        lds128(a[i], as + i * 1024);

#pragma unroll
                    for (int jh = 0; jh < 2; jh++) {
                        uint32_t b[4][4];
#pragma unroll
                        for (int jj = 0; jj < 4; jj++) {
                            int j = jh * 4 + jj;
                            uint32_t base = (j & 1) ? bsO : bsE;
                            lds128(b[jj], base + (j >> 1) * 1024);
                        }
#pragma unroll
                        for (int i = 0; i < 8; i++)
#pragma unroll
                            for (int jj = 0; jj < 4; jj++) {
                                int& acc = cd[i][jh * 4 + jj];
                                dp4a_acc(acc, a[i][0], b[jj][0]);
                                dp4a_acc(acc, a[i][1], b[jj][1]);
                                dp4a_acc(acc, a[i][2], b[jj][2]);
                                dp4a_acc(acc, a[i][3], b[jj][3]);
                            }
                    }
                }
                g++;
            }

            // ---- two-phase merged epilogue ----
            int n0g = (T & 31) * BN + wn * 32 + tn;
            int m0base = (T >> 5) * BM;
            float scv[8], biv[8];
#pragma unroll
            for (int j = 0; j < 8; j++) {
                scv[j] = g_sc[n0g + 4 * j];
                biv[j] = bias[n0g + 4 * j];
            }
            const int* part = (const int*)(smem + SM_PART);
            int pcol = wn * 32 + tn;

#pragma unroll
            for (int ph = 0; ph < 2; ph++) {
                asm volatile("bar.sync 3, 512;" ::: "memory");   // phase partials ready
#pragma unroll
                for (int ii = 0; ii < 4; ii++) {
                    // phase 0: i = 0,1,4,5 ; phase 1: i = 2,3,6,7
                    int i = (ii & 1) + ((ii >> 1) << 2) + ph * 2;
                    int r = wm * 64 + tm + 8 * i;
                    int pidx = ((r >> 5) << 4) + (r & 15);
                    const int* prw = part + pidx * PART_STRIDE + pcol;
                    float* orow = out + (size_t)(m0base + r) * NDIM + n0g;
#pragma unroll
                    for (int j = 0; j < 8; j++)
                        orow[4 * j] = (float)(cd[i][j] + prw[4 * j]) * scv[j] + biv[j];
                }
                asm volatile("membar.cta;" ::: "memory");
                asm volatile("bar.arrive 4, 512;" ::: "memory"); // phase consumed
            }
        }
    }
}

// -------- launch --------
extern "C" void kernel_launch(void* const* d_in, const int* in_sizes, int n_in,
                              void* d_out, int out_size) {
    const float* x        = (const float*)d_in[0];
    const float* in_scale = (const float*)d_in[1];
    const float* act      = (const float*)d_in[2];
    const int*   w        = (const int*)d_in[3];
    const float* w_scale  = (const float*)d_in[4];
    const float* bias     = (const float*)d_in[5];
    float* out = (float*)d_out;

    int M = in_sizes[0] / KDIM;  // 8192

    cudaFuncSetAttribute(gemm_kernel, cudaFuncAttributeMaxDynamicSharedMemorySize, SMEM_TOTAL);

    precomp_scales<<<(KDIM + 255) / 256, 256>>>(in_scale, act, w_scale);

    int xa4 = (M * KDIM) / 4;
    quant_x<<<(xa4 + 255) / 256, 256>>>(x, xa4);

    int wb4 = (NDIM * KDIM) / 4;
    conv_w<<<(wb4 + 255) / 256, 256>>>(w, wb4);

    gemm_kernel<<<GRID, 512, SMEM_TOTAL>>>(bias, out);
}

// round 13
// speedup vs baseline: 1.1402x; 1.0045x over previous
#include <cuda_runtime.h>
#include <cuda_bf16.h>
#include <cstdint>
#include <cstddef>

// Fixed problem dims: B=4, S=2048 -> M=8192, K=4096, N=4096
#define KDIM 4096
#define NDIM 4096
#define MMAX 8192

#define BM 128
#define BN 128
#define BK 128
#define KT (KDIM / BK)      // 32 k-chunks
#define KI 18               // k-chunks done by IMMA warps (even)
#define KD (KT - KI)        // 14 k-chunks done by dp4a warps
#define NPAIR (KI / 2)      // 9 IMMA chunk-pairs

#define TILES_TOT ((MMAX / BM) * (NDIM / BN))  // 2048
#define GRID 148                                // persistent CTAs (1/SM)

#define STAGE_BYTES (BM * BK + BN * BK)        // 32768
#define SM_DP   (4 * STAGE_BYTES)               // 131072 (IMMA: 4 buffers = 2 pairs)
#define SM_PART (SM_DP + 2 * STAGE_BYTES)       // 196608 (dp4a: 2 buffers)
#define PART_STRIDE 132                         // padded int32 row stride
#define PHASE_INTS (32 * PART_STRIDE)           // one 32-row phase buffer
#define SMEM_TOTAL (SM_PART + 2 * PHASE_INTS * 4)  // 230400

// -------- device scratch --------
__device__ int8_t g_A8[(size_t)MMAX * KDIM];
__device__ int8_t g_B8[(size_t)NDIM * KDIM];
__device__ float  g_comb[KDIM];
__device__ float  g_sc[NDIM];

// -------- helpers --------
__device__ __forceinline__ uint32_t smem_u32(const void* p) {
    uint32_t a;
    asm("{ .reg .u64 t; cvta.to.shared.u64 t, %1; cvt.u32.u64 %0, t; }" : "=r"(a) : "l"(p));
    return a;
}
__device__ __forceinline__ void cp16(uint32_t s, const void* g) {
    asm volatile("cp.async.cg.shared.global [%0], [%1], 16;" :: "r"(s), "l"(g));
}
__device__ __forceinline__ void ldsm4(uint32_t* d, uint32_t addr) {
    asm volatile("ldmatrix.sync.aligned.m8n8.x4.shared.b16 {%0,%1,%2,%3}, [%4];"
                 : "=r"(d[0]), "=r"(d[1]), "=r"(d[2]), "=r"(d[3]) : "r"(addr));
}
__device__ __forceinline__ void imma(int* c, const uint32_t* a, const uint32_t* b) {
    asm volatile(
        "mma.sync.aligned.m16n8k32.row.col.s32.s8.s8.s32 "
        "{%0,%1,%2,%3}, {%4,%5,%6,%7}, {%8,%9}, {%0,%1,%2,%3};"
        : "+r"(c[0]), "+r"(c[1]), "+r"(c[2]), "+r"(c[3])
        : "r"(a[0]), "r"(a[1]), "r"(a[2]), "r"(a[3]), "r"(b[0]), "r"(b[1]));
}
__device__ __forceinline__ void dp4a_acc(int& c, uint32_t a, uint32_t b) {
    asm volatile("dp4a.s32.s32 %0, %1, %2, %0;" : "+r"(c) : "r"(a), "r"(b));
}
__device__ __forceinline__ void lds128(uint32_t* d, uint32_t addr) {
    asm volatile("ld.shared.v4.b32 {%0,%1,%2,%3}, [%4];"
                 : "=r"(d[0]), "=r"(d[1]), "=r"(d[2]), "=r"(d[3]) : "r"(addr));
}

// -------- preprocessing --------
__global__ void precomp_scales(const float* __restrict__ in_scale,
                               const float* __restrict__ act,
                               const float* __restrict__ w_scale) {
    int i = blockIdx.x * blockDim.x + threadIdx.x;
    float a = act[0];
    if (i < KDIM) g_comb[i] = __fdiv_rn(in_scale[i], a);
    if (i < NDIM) g_sc[i] = a * w_scale[i];
}

__global__ void quant_x(const float* __restrict__ x, int total4) {
    int i = blockIdx.x * blockDim.x + threadIdx.x;
    if (i >= total4) return;
    float4 v = reinterpret_cast<const float4*>(x)[i];
    int col = (i & (KDIM / 4 - 1)) * 4;
    int q0 = min(max(__float2int_rn(v.x * g_comb[col + 0]), -127), 127);
    int q1 = min(max(__float2int_rn(v.y * g_comb[col + 1]), -127), 127);
    int q2 = min(max(__float2int_rn(v.z * g_comb[col + 2]), -127), 127);
    int q3 = min(max(__float2int_rn(v.w * g_comb[col + 3]), -127), 127);
    uint32_t p = (uint32_t)(q0 & 0xFF) | ((uint32_t)(q1 & 0xFF) << 8) |
                 ((uint32_t)(q2 & 0xFF) << 16) | ((uint32_t)(q3 & 0xFF) << 24);
    reinterpret_cast<uint32_t*>(g_A8)[i] = p;
}

__global__ void conv_w(const int* __restrict__ w, int total4) {
    int i = blockIdx.x * blockDim.x + threadIdx.x;
    if (i >= total4) return;
    int4 v = reinterpret_cast<const int4*>(w)[i];
    uint32_t p = (uint32_t)(v.x & 0xFF) | ((uint32_t)(v.y & 0xFF) << 8) |
                 ((uint32_t)(v.z & 0xFF) << 16) | ((uint32_t)(v.w & 0xFF) << 24);
    reinterpret_cast<uint32_t*>(g_B8)[i] = p;
}

// -------- shared tile loader (A then B, XOR-swizzled, 256 threads) --------
__device__ __forceinline__ void load_stage(uint32_t sm, const char* gA, const char* gB,
                                           int kt, int t) {
    const char* ga = gA + (size_t)kt * BK;
    const char* gb = gB + (size_t)kt * BK;
#pragma unroll
    for (int i = 0; i < 4; i++) {
        int slot = t + i * 256;
        int row = slot >> 3, seg = slot & 7;
        cp16(sm + row * 128 + ((seg ^ (row & 7)) << 4),
             ga + (size_t)row * KDIM + seg * 16);
    }
#pragma unroll
    for (int i = 0; i < 4; i++) {
        int slot = t + i * 256;
        int row = slot >> 3, seg = slot & 7;
        cp16(sm + BM * 128 + row * 128 + ((seg ^ (row & 7)) << 4),
             gb + (size_t)row * KDIM + seg * 16);
    }
}

// ---- persistent hybrid GEMM: warps 8-15 IMMA (hi-prio), warps 0-7 dp4a ----
// Handoff barriers (parity-split, each holds at most one pending arrive-set):
//   ready  even/odd : bar3 / bar6   (IMMA arrives, dp4a syncs)
//   consumed even/odd: bar4 / bar5  (dp4a arrives, IMMA syncs)
__global__ __launch_bounds__(512, 1)
void gemm_kernel(const float* __restrict__ bias, float* __restrict__ out) {
    extern __shared__ __align__(1024) char smem[];
    uint32_t sb = smem_u32(smem);
    int tid = threadIdx.x;
    int bid = blockIdx.x;
    int nt = (TILES_TOT - bid + GRID - 1) / GRID;   // tiles this CTA processes

    if (tid >= 256) {
        // ===== IMMA group (warps 8-15): 2-pair pipeline =====
        int it = tid - 256;
        int lane = it & 31, wid = it >> 5;
        int warp_m = wid >> 1, warp_n = wid & 1;     // 4x2 warps, warp tile 32x64

        int tq = lane >> 3, r = lane & 7;
        int rowA[2], rowB[4];
#pragma unroll
        for (int im = 0; im < 2; im++) rowA[im] = warp_m * 32 + im * 16 + (tq & 1) * 8 + r;
        int segA = tq >> 1;
#pragma unroll
        for (int nb = 0; nb < 4; nb++) rowB[nb] = warp_n * 64 + nb * 16 + (tq >> 1) * 8 + r;
        int segB = tq & 1;

        int pidx0 = warp_m * 8 + (lane >> 2);        // row within 32-row phase buffer
        int cl = warp_n * 64 + (lane & 3) * 2;

        int ld_tile = bid, ld_pair = 0;
        const char* lA = (const char*)g_A8 + (size_t)(ld_tile >> 5) * BM * KDIM;
        const char* lB = (const char*)g_B8 + (size_t)(ld_tile & 31) * BN * KDIM;

        load_stage(sb + 0 * STAGE_BYTES, lA, lB, 0, it);
        load_stage(sb + 1 * STAGE_BYTES, lA, lB, 1, it);
        asm volatile("cp.async.commit_group;" ::: "memory");

        int P = 0;   // global pair counter; slot-pair = P & 1

#pragma unroll 1
        for (int t = 0; t < nt; t++) {
            int c[2][8][4];
#pragma unroll
            for (int im = 0; im < 2; im++)
#pragma unroll
                for (int n8 = 0; n8 < 8; n8++)
#pragma unroll
                    for (int q = 0; q < 4; q++) c[im][n8][q] = 0;

#pragma unroll 1
            for (int p = 0; p < NPAIR; p++) {
                asm volatile("bar.sync 1, 256;" ::: "memory");   // pair P-1 buffers free

                ld_pair++;
                if (ld_pair == NPAIR) {
                    ld_pair = 0;
                    ld_tile += GRID;
                    if (ld_tile < TILES_TOT) {
                        lA = (const char*)g_A8 + (size_t)(ld_tile >> 5) * BM * KDIM;
                        lB = (const char*)g_B8 + (size_t)(ld_tile & 31) * BN * KDIM;
                    }
                }
                if (ld_tile < TILES_TOT) {
                    uint32_t s0 = sb + (uint32_t)((((P + 1) & 1) * 2) * STAGE_BYTES);
                    load_stage(s0, lA, lB, ld_pair * 2, it);
                    load_stage(s0 + STAGE_BYTES, lA, lB, ld_pair * 2 + 1, it);
                }
                asm volatile("cp.async.commit_group;" ::: "memory");
                asm volatile("cp.async.wait_group 1;" ::: "memory");  // pair P resident

#pragma unroll
                for (int u = 0; u < 2; u++) {
                    uint32_t sA = sb + (uint32_t)((((P & 1) * 2) + u) * STAGE_BYTES);
                    uint32_t sB = sA + BM * 128;
#pragma unroll
                    for (int j = 0; j < 4; j++) {
                        uint32_t a[2][4];
#pragma unroll
                        for (int im = 0; im < 2; im++) {
                            int seg = 2 * j + segA;
                            ldsm4(a[im], sA + rowA[im] * 128 + ((seg ^ (rowA[im] & 7)) << 4));
                        }
                        uint32_t bfr[8][2];
#pragma unroll
                        for (int nb = 0; nb < 4; nb++) {
                            uint32_t r4[4];
                            int seg = 2 * j + segB;
                            ldsm4(r4, sB + rowB[nb] * 128 + ((seg ^ (rowB[nb] & 7)) << 4));
                            bfr[2 * nb][0] = r4[0]; bfr[2 * nb][1] = r4[1];
                            bfr[2 * nb + 1][0] = r4[2]; bfr[2 * nb + 1][1] = r4[3];
                        }
#pragma unroll
                        for (int im = 0; im < 2; im++)
#pragma unroll
                            for (int n8 = 0; n8 < 8; n8++)
                                imma(c[im][n8], a[im], bfr[n8]);
                    }
                }
                P++;
            }

            // ---- 4-phase ping-pong dump: phase k = im*2+half, buffer k&1 ----
            int* part0 = (int*)(smem + SM_PART);
#pragma unroll
            for (int k = 0; k < 4; k++) {
                if (t > 0 || k >= 2) {
                    if (k & 1) asm volatile("bar.sync 5, 512;" ::: "memory");
                    else       asm volatile("bar.sync 4, 512;" ::: "memory");
                }
                int im = k >> 1, half = k & 1;
                int* part = part0 + (k & 1) * PHASE_INTS;
#pragma unroll
                for (int n8 = 0; n8 < 8; n8++) {
                    int lc = cl + n8 * 8;
                    *reinterpret_cast<int2*>(&part[pidx0 * PART_STRIDE + lc]) =
                        make_int2(c[im][n8][half * 2], c[im][n8][half * 2 + 1]);
                }
                asm volatile("membar.cta;" ::: "memory");
                if (k & 1) asm volatile("bar.arrive 6, 512;" ::: "memory");
                else       asm volatile("bar.arrive 3, 512;" ::: "memory");
            }
        }
    } else {
        // ===== dp4a group (warps 0-7): continuous 2-stage stream + phased merge =====
        int dt = tid;
        int dl = dt & 31, dwid = dt >> 5;
        int wm = dwid >> 2, wn = dwid & 3;   // 2x4 warps, warp tile 64x32
        int tm = dl >> 2, tn = dl & 3;       // 8x4 threads, thread tile 8x8

        uint32_t dbase = sb + SM_DP;

        int ld_tile = bid, ld_kt = 0;
        const char* lA = (const char*)g_A8 + (size_t)(ld_tile >> 5) * BM * KDIM;
        const char* lB = (const char*)g_B8 + (size_t)(ld_tile & 31) * BN * KDIM;

        load_stage(dbase + 0 * STAGE_BYTES, lA, lB, KI + 0, dt);
        asm volatile("cp.async.commit_group;" ::: "memory");

        int g = 0;   // global chunk counter; buffer = g & 1

#pragma unroll 1
        for (int t = 0; t < nt; t++) {
            int T = bid + t * GRID;

            int cd[8][8];
#pragma unroll
            for (int i = 0; i < 8; i++)
#pragma unroll
                for (int j = 0; j < 8; j++) cd[i][j] = 0;

#pragma unroll 1
            for (int kt = 0; kt < KD; kt++) {
                asm volatile("cp.async.wait_group 0;" ::: "memory");
                asm volatile("bar.sync 2, 256;" ::: "memory");

                ld_kt++;
                if (ld_kt == KD) {
                    ld_kt = 0;
                    ld_tile += GRID;
                    if (ld_tile < TILES_TOT) {
                        lA = (const char*)g_A8 + (size_t)(ld_tile >> 5) * BM * KDIM;
                        lB = (const char*)g_B8 + (size_t)(ld_tile & 31) * BN * KDIM;
                    }
                }
                if (ld_tile < TILES_TOT)
                    load_stage(dbase + (uint32_t)(((g + 1) & 1) * STAGE_BYTES), lA, lB,
                               KI + ld_kt, dt);
                asm volatile("cp.async.commit_group;" ::: "memory");

                uint32_t sA = dbase + (uint32_t)((g & 1) * STAGE_BYTES);
                uint32_t sB = sA + BM * 128;

                uint32_t aA = sA + (uint32_t)((wm * 64 + tm) * 128 + (tm << 4));
                uint32_t bE = sB + (uint32_t)((wn * 32 + tn) * 128 + (tn << 4));
                uint32_t bO = bE + 512 + 64;

#pragma unroll 1
                for (int seg = 0; seg < 8; seg++) {
                    uint32_t as  = aA ^ (uint32_t)(seg << 4);
                    uint32_t bsE = bE ^ (uint32_t)(seg << 4);
                    uint32_t bsO = bO ^ (uint32_t)(seg << 4);

                    uint32_t a[8][4];
#pragma unroll
                    for (int i = 0; i < 8; i++)
                        lds128(a[i], as + i * 1024);

#pragma unroll
                    for (int jh = 0; jh < 2; jh++) {
                        uint32_t b[4][4];
#pragma unroll
                        for (int jj = 0; jj < 4; jj++) {
                            int j = jh * 4 + jj;
                            uint32_t base = (j & 1) ? bsO : bsE;
                            lds128(b[jj], base + (j >> 1) * 1024);
                        }
#pragma unroll
                        for (int i = 0; i < 8; i++)
#pragma unroll
                            for (int jj = 0; jj < 4; jj++) {
                                int& acc = cd[i][jh * 4 + jj];
                                dp4a_acc(acc, a[i][0], b[jj][0]);
                                dp4a_acc(acc, a[i][1], b[jj][1]);
                                dp4a_acc(acc, a[i][2], b[jj][2]);
                                dp4a_acc(acc, a[i][3], b[jj][3]);
                            }
                    }
                }
                g++;
            }

            // ---- 4-phase merged epilogue (phase k holds rows with (r>>3)&3==k) ----
            int n0g = (T & 31) * BN + wn * 32 + tn;
            int m0base = (T >> 5) * BM;
            float scv[8], biv[8];
#pragma unroll
            for (int j = 0; j < 8; j++) {
                scv[j] = g_sc[n0g + 4 * j];
                biv[j] = bias[n0g + 4 * j];
            }
            const int* part0 = (const int*)(smem + SM_PART);
            int pcol = wn * 32 + tn;

#pragma unroll
            for (int k = 0; k < 4; k++) {
                if (k & 1) asm volatile("bar.sync 6, 512;" ::: "memory");
                else       asm volatile("bar.sync 3, 512;" ::: "memory");
                const int* part = part0 + (k & 1) * PHASE_INTS;
#pragma unroll
                for (int h = 0; h < 2; h++) {
                    int i = k + 4 * h;
                    int r = wm * 64 + tm + 8 * i;
                    int pidx = wm * 16 + 8 * h + tm;
                    const int* prw = part + pidx * PART_STRIDE + pcol;
                    float* orow = out + (size_t)(m0base + r) * NDIM + n0g;
#pragma unroll
                    for (int j = 0; j < 8; j++)
                        orow[4 * j] = (float)(cd[i][j] + prw[4 * j]) * scv[j] + biv[j];
                }
                asm volatile("membar.cta;" ::: "memory");
                if (k & 1) asm volatile("bar.arrive 5, 512;" ::: "memory");
                else       asm volatile("bar.arrive 4, 512;" ::: "memory");
            }
        }
    }
}

// -------- launch --------
extern "C" void kernel_launch(void* const* d_in, const int* in_sizes, int n_in,
                              void* d_out, int out_size) {
    const float* x        = (const float*)d_in[0];
    const float* in_scale = (const float*)d_in[1];
    const float* act      = (const float*)d_in[2];
    const int*   w        = (const int*)d_in[3];
    const float* w_scale  = (const float*)d_in[4];
    const float* bias     = (const float*)d_in[5];
    float* out = (float*)d_out;

    int M = in_sizes[0] / KDIM;  // 8192

    cudaFuncSetAttribute(gemm_kernel, cudaFuncAttributeMaxDynamicSharedMemorySize, SMEM_TOTAL);

    precomp_scales<<<(KDIM + 255) / 256, 256>>>(in_scale, act, w_scale);

    int xa4 = (M * KDIM) / 4;
    quant_x<<<(xa4 + 255) / 256, 256>>>(x, xa4);

    int wb4 = (NDIM * KDIM) / 4;
    conv_w<<<(wb4 + 255) / 256, 256>>>(w, wb4);

    gemm_kernel<<<GRID, 512, SMEM_TOTAL>>>(bias, out);
}